// round 11
// baseline (speedup 1.0000x reference)
#include <cuda_runtime.h>

#define TT 1024
#define HH 128
#define BB 256
#define NTHREADS 256
#define K2_THREADS 256

// 256*1024*128 floats = 128 MB scratch for hidden-state sequence [B,T,H]
__device__ float g_hseq[(size_t)BB * TT * HH];

__device__ __forceinline__ unsigned long long ffma2(unsigned long long a,
                                                    unsigned long long b,
                                                    unsigned long long c) {
    unsigned long long d;
    asm("fma.rn.f32x2 %0, %1, %2, %3;" : "=l"(d) : "l"(a), "l"(b), "l"(c));
    return d;
}

__device__ __forceinline__ unsigned long long addf2(unsigned long long a,
                                                    unsigned long long b) {
    unsigned long long d;
    asm("add.rn.f32x2 %0, %1, %2;" : "=l"(d) : "l"(a), "l"(b));
    return d;
}

__device__ __forceinline__ float2 unpack_f32x2(unsigned long long v) {
    float2 f;
    asm("mov.b64 {%0, %1}, %2;" : "=f"(f.x), "=f"(f.y) : "l"(v));
    return f;
}

// ---------------------------------------------------------------------------
// Kernel 1: recurrence. One CTA = ONE batch row, 256 threads.
// Thread (h, half) computes half of unit h's dot (64 MACs = 32 FFMA2);
// lanes 2j/2j+1 combine via shfl_xor(1). 2 CTAs/SM -> 4 warps/SMSP for
// cross-row latency hiding.
// ---------------------------------------------------------------------------
__global__ __launch_bounds__(NTHREADS, 2)
void rnn_rec_kernel(const float* __restrict__ x,      // [B, T, 1]
                    const float* __restrict__ W_ih,   // [H, 1]
                    const float* __restrict__ W_hh,   // [H, H]
                    const float* __restrict__ b_ih,   // [H]
                    const float* __restrict__ b_hh)   // [H]
{
    __shared__ __align__(16) float xs[TT];        // 4 KB input preload
    __shared__ __align__(16) float hs[2][HH];     // double-buffered h

    const int tid  = threadIdx.x;
    const int h    = tid >> 1;          // hidden unit (0..127)
    const int half = tid & 1;           // which 64-wide half of the dot
    const int b    = blockIdx.x;

    // ---- my 64 weights: W_hh[h][64*half .. 64*half+63] -> 32 packed f32x2 ----
    unsigned long long w[HH / 4];
    {
        const ulonglong2* wrow =
            (const ulonglong2*)(W_hh + h * HH + 64 * half);
        #pragma unroll
        for (int j = 0; j < HH / 8; j++) {          // 16 LDG.128
            ulonglong2 v = wrow[j];
            w[2 * j]     = v.x;
            w[2 * j + 1] = v.y;
        }
    }
    const float wih  = W_ih[h];
    const float bias = b_ih[h] + b_hh[h];

    // ---- preload x for this row ----
    for (int i = tid; i < TT; i += NTHREADS)
        xs[i] = x[b * TT + i];

    if (half == 0) hs[0][h] = 0.0f;
    __syncthreads();

    float* hout = g_hseq + (size_t)b * TT * HH + h;

    for (int t = 0; t < TT; t++) {
        const int cur = t & 1;
        const int nxt = cur ^ 1;

        // 64-wide half-dot via packed f32x2 FMA
        unsigned long long a0 = 0ull, a1 = 0ull, a2 = 0ull, a3 = 0ull;
        const ulonglong2* hv = (const ulonglong2*)&hs[cur][64 * half];
        #pragma unroll
        for (int j = 0; j < 8; j++) {
            ulonglong2 p = hv[2 * j];
            ulonglong2 q = hv[2 * j + 1];
            a0 = ffma2(p.x, w[4 * j],     a0);
            a1 = ffma2(p.y, w[4 * j + 1], a1);
            a2 = ffma2(q.x, w[4 * j + 2], a2);
            a3 = ffma2(q.y, w[4 * j + 3], a3);
        }
        unsigned long long s = addf2(addf2(a0, a1), addf2(a2, a3));
        float2 f = unpack_f32x2(s);
        float part = f.x + f.y;
        float dot  = part + __shfl_xor_sync(0xffffffffu, part, 1);

        float pre = fmaf(xs[t], wih, dot + bias);

        // tanh(x) = 1 - 2/(exp(2x)+1)   (EX2 + RCP, ~1e-6 rel err)
        float e  = __expf(pre + pre);
        float hn = 1.0f - __fdividef(2.0f, e + 1.0f);

        if (half == 0) {
            hs[nxt][h] = hn;
            hout[(size_t)t * HH] = hn;    // 16 even lanes, 64B/warp
        }
        __syncthreads();
    }
}

// ---------------------------------------------------------------------------
// Kernel 2: streaming logits. out[b,t,c] = sum_h hseq[b,t,h]*W_fc[c,h] + b_fc[c]
// ---------------------------------------------------------------------------
__global__ __launch_bounds__(K2_THREADS)
void rnn_fc_kernel(const float* __restrict__ W_fc,   // [2, H]
                   const float* __restrict__ b_fc,   // [2]
                   float* __restrict__ out)          // [B, T, 2]
{
    __shared__ __align__(16) float wf[2][HH];
    __shared__ float bf[2];

    const int tid = threadIdx.x;
    if (tid < HH) {
        wf[0][tid] = W_fc[tid];
        wf[1][tid] = W_fc[HH + tid];
    }
    if (tid < 2) bf[tid] = b_fc[tid];
    __syncthreads();

    const size_t r = (size_t)blockIdx.x * K2_THREADS + tid;   // row in [0, B*T)
    const float4* hv = (const float4*)(g_hseq + r * HH);
    const float4* w0 = (const float4*)wf[0];
    const float4* w1 = (const float4*)wf[1];

    float acc0 = 0.0f, acc1 = 0.0f;
    #pragma unroll
    for (int j = 0; j < HH / 4; j++) {
        float4 v  = __ldcs(&hv[j]);     // streaming: don't thrash L1
        float4 a  = w0[j];
        float4 c  = w1[j];
        acc0 = fmaf(v.x, a.x, acc0); acc0 = fmaf(v.y, a.y, acc0);
        acc0 = fmaf(v.z, a.z, acc0); acc0 = fmaf(v.w, a.w, acc0);
        acc1 = fmaf(v.x, c.x, acc1); acc1 = fmaf(v.y, c.y, acc1);
        acc1 = fmaf(v.z, c.z, acc1); acc1 = fmaf(v.w, c.w, acc1);
    }
    float2 res = make_float2(acc0 + bf[0], acc1 + bf[1]);
    ((float2*)out)[r] = res;           // coalesced 8B/thread
}

extern "C" void kernel_launch(void* const* d_in, const int* in_sizes, int n_in,
                              void* d_out, int out_size) {
    const float* x    = (const float*)d_in[0];
    const float* W_ih = (const float*)d_in[1];
    const float* W_hh = (const float*)d_in[2];
    const float* b_ih = (const float*)d_in[3];
    const float* b_hh = (const float*)d_in[4];
    const float* W_fc = (const float*)d_in[5];
    const float* b_fc = (const float*)d_in[6];
    float* out = (float*)d_out;

    rnn_rec_kernel<<<BB, NTHREADS>>>(x, W_ih, W_hh, b_ih, b_hh);
    rnn_fc_kernel<<<(BB * TT) / K2_THREADS, K2_THREADS>>>(W_fc, b_fc, out);
}

// round 13
// speedup vs baseline: 1.6596x; 1.6596x over previous
#include <cuda_runtime.h>
#include <cuda_fp16.h>

#define TT 1024
#define HH 128
#define BB 256
#define BPC 2          // batches per CTA
#define NTHREADS 256
#define K2_THREADS 256

// 256*1024*128 halves = 64 MB scratch for hidden-state sequence [B,T,H]
__device__ __half g_hseq_h[(size_t)BB * TT * HH];

__device__ __forceinline__ unsigned long long ffma2(unsigned long long a,
                                                    unsigned long long b,
                                                    unsigned long long c) {
    unsigned long long d;
    asm("fma.rn.f32x2 %0, %1, %2, %3;" : "=l"(d) : "l"(a), "l"(b), "l"(c));
    return d;
}

__device__ __forceinline__ unsigned long long addf2(unsigned long long a,
                                                    unsigned long long b) {
    unsigned long long d;
    asm("add.rn.f32x2 %0, %1, %2;" : "=l"(d) : "l"(a), "l"(b));
    return d;
}

__device__ __forceinline__ unsigned long long pack2(float lo, float hi) {
    unsigned long long d;
    asm("mov.b64 %0, {%1, %2};" : "=l"(d) : "f"(lo), "f"(hi));
    return d;
}

__device__ __forceinline__ float2 unpack_f32x2(unsigned long long v) {
    float2 f;
    asm("mov.b64 {%0, %1}, %2;" : "=f"(f.x), "=f"(f.y) : "l"(v));
    return f;
}

// ---------------------------------------------------------------------------
// Kernel 1: serial recurrence (R4 structure). One CTA = 2 batch rows;
// thread (bl, h) owns hidden unit h of row bl; rows decoupled via named
// barriers over their own 4 warps. Recurrence math is pure fp32; only the
// exported hidden state is cast to fp16 for the streaming fc kernel.
// ---------------------------------------------------------------------------
__global__ __launch_bounds__(NTHREADS, 1)
void rnn_rec_kernel(const float* __restrict__ x,      // [B, T, 1]
                    const float* __restrict__ W_ih,   // [H, 1]
                    const float* __restrict__ W_hh,   // [H, H]
                    const float* __restrict__ b_ih,   // [H]
                    const float* __restrict__ b_hh)   // [H]
{
    __shared__ __align__(16) float xs[BPC][TT];        // 8 KB input preload
    __shared__ __align__(16) float hs[2][BPC][HH];     // double-buffered h

    const int tid = threadIdx.x;
    const int bl  = tid >> 7;         // batch-local 0/1
    const int h   = tid & (HH - 1);
    const int b   = blockIdx.x * BPC + bl;
    const int bar = bl + 1;           // named barrier id: this row's 4 warps

    // ---- W_hh row h -> 64 packed f32x2 registers ----
    unsigned long long w[HH / 2];
    {
        const ulonglong2* wrow = (const ulonglong2*)(W_hh + h * HH);
        #pragma unroll
        for (int j = 0; j < HH / 4; j++) {
            ulonglong2 v = wrow[j];
            w[2 * j]     = v.x;
            w[2 * j + 1] = v.y;
        }
    }
    const float wih  = W_ih[h];
    const float bias = b_ih[h] + b_hh[h];

    // ---- preload x for this row (group-local; covered by named barrier) ----
    for (int i = h; i < TT; i += HH)
        xs[bl][i] = x[b * TT + i];

    hs[0][bl][h] = 0.0f;
    asm volatile("bar.sync %0, 128;" :: "r"(bar) : "memory");

    __half* hout = g_hseq_h + (size_t)b * TT * HH + h;

    for (int t = 0; t < TT; t++) {
        const int cur = t & 1;
        const int nxt = cur ^ 1;

        // x-projection + bias folded into accumulator init (off critical tail)
        const float xb = fmaf(xs[bl][t], wih, bias);

        // 128-wide dot via packed f32x2 FMA, 4 independent chains
        unsigned long long a0 = pack2(xb, 0.0f);
        unsigned long long a1 = 0ull, a2 = 0ull, a3 = 0ull;
        const ulonglong2* hv = (const ulonglong2*)&hs[cur][bl][0];
        #pragma unroll
        for (int j = 0; j < HH / 4; j += 2) {
            ulonglong2 p = hv[j];
            a0 = ffma2(p.x, w[2 * j],     a0);
            a1 = ffma2(p.y, w[2 * j + 1], a1);
            ulonglong2 q = hv[j + 1];
            a2 = ffma2(q.x, w[2 * j + 2], a2);
            a3 = ffma2(q.y, w[2 * j + 3], a3);
        }
        unsigned long long s = addf2(addf2(a0, a1), addf2(a2, a3));
        float2 f  = unpack_f32x2(s);
        float pre = f.x + f.y;

        // tanh(x) = 1 - 2/(exp(2x)+1)   (EX2 + RCP, ~1e-6 rel err; safe vs
        // MUFU.TANH whose 5e-4 abs err compounds over 1024 steps)
        float e  = __expf(pre + pre);
        float hn = 1.0f - __fdividef(2.0f, e + 1.0f);

        hs[nxt][bl][h] = hn;
        hout[(size_t)t * HH] = __float2half(hn);   // fp16 export for fc

        asm volatile("bar.sync %0, 128;" :: "r"(bar) : "memory");
    }
}

// ---------------------------------------------------------------------------
// Kernel 2: streaming logits from fp16 hidden states (64 MB total).
// out[b,t,c] = sum_h h[b,t,h]*W_fc[c,h] + b_fc[c];  fp32 accumulation.
// ---------------------------------------------------------------------------
__global__ __launch_bounds__(K2_THREADS)
void rnn_fc_kernel(const float* __restrict__ W_fc,   // [2, H]
                   const float* __restrict__ b_fc,   // [2]
                   float* __restrict__ out)          // [B, T, 2]
{
    __shared__ __align__(16) float wf[2][HH];
    __shared__ float bf[2];

    const int tid = threadIdx.x;
    if (tid < HH) {
        wf[0][tid] = W_fc[tid];
        wf[1][tid] = W_fc[HH + tid];
    }
    if (tid < 2) bf[tid] = b_fc[tid];
    __syncthreads();

    const size_t r = (size_t)blockIdx.x * K2_THREADS + tid;   // row in [0, B*T)
    const uint4* hv = (const uint4*)(g_hseq_h + r * HH);      // 16 x 16B = 128 halves

    float acc0 = 0.0f, acc1 = 0.0f;
    #pragma unroll
    for (int j = 0; j < HH / 8; j++) {          // 16 LDG.128
        uint4 v = __ldcs(&hv[j]);
        const __half2* hp = (const __half2*)&v;
        #pragma unroll
        for (int k = 0; k < 4; k++) {
            float2 hf = __half22float2(hp[k]);
            int idx = j * 8 + k * 2;
            acc0 = fmaf(hf.x, wf[0][idx],     acc0);
            acc0 = fmaf(hf.y, wf[0][idx + 1], acc0);
            acc1 = fmaf(hf.x, wf[1][idx],     acc1);
            acc1 = fmaf(hf.y, wf[1][idx + 1], acc1);
        }
    }
    float2 res = make_float2(acc0 + bf[0], acc1 + bf[1]);
    ((float2*)out)[r] = res;           // coalesced 8B/thread
}

extern "C" void kernel_launch(void* const* d_in, const int* in_sizes, int n_in,
                              void* d_out, int out_size) {
    const float* x    = (const float*)d_in[0];
    const float* W_ih = (const float*)d_in[1];
    const float* W_hh = (const float*)d_in[2];
    const float* b_ih = (const float*)d_in[3];
    const float* b_hh = (const float*)d_in[4];
    const float* W_fc = (const float*)d_in[5];
    const float* b_fc = (const float*)d_in[6];
    float* out = (float*)d_out;

    rnn_rec_kernel<<<BB / BPC, NTHREADS>>>(x, W_ih, W_hh, b_ih, b_hh);
    rnn_fc_kernel<<<(BB * TT) / K2_THREADS, K2_THREADS>>>(W_fc, b_fc, out);
}

// round 14
// speedup vs baseline: 1.6659x; 1.0038x over previous
#include <cuda_runtime.h>
#include <cuda_fp16.h>

#define TT 1024
#define HH 128
#define BB 256
#define BPC 2          // batches per CTA
#define NTHREADS 256
#define K2_THREADS 256

// 256*1024*128 halves = 64 MB scratch for hidden-state sequence [B,T,H]
__device__ __half g_hseq_h[(size_t)BB * TT * HH];

__device__ __forceinline__ unsigned long long ffma2(unsigned long long a,
                                                    unsigned long long b,
                                                    unsigned long long c) {
    unsigned long long d;
    asm("fma.rn.f32x2 %0, %1, %2, %3;" : "=l"(d) : "l"(a), "l"(b), "l"(c));
    return d;
}

__device__ __forceinline__ unsigned long long addf2(unsigned long long a,
                                                    unsigned long long b) {
    unsigned long long d;
    asm("add.rn.f32x2 %0, %1, %2;" : "=l"(d) : "l"(a), "l"(b));
    return d;
}

__device__ __forceinline__ unsigned long long pack2(float lo, float hi) {
    unsigned long long d;
    asm("mov.b64 %0, {%1, %2};" : "=l"(d) : "f"(lo), "f"(hi));
    return d;
}

__device__ __forceinline__ float2 unpack_f32x2(unsigned long long v) {
    float2 f;
    asm("mov.b64 {%0, %1}, %2;" : "=f"(f.x), "=f"(f.y) : "l"(v));
    return f;
}

// ---------------------------------------------------------------------------
// Kernel 1: serial recurrence. One CTA = 2 batch rows; thread (bl, h) owns
// hidden unit h of row bl; rows decoupled via named barriers over their own
// 4 warps. NEW this round: row 1 is skewed by a ~320-cycle deterministic
// delay before its first barrier, forcing the two rows into anti-phase so
// each SMSP overlaps one row's FMA burst with the other row's serial tail.
// ---------------------------------------------------------------------------
__global__ __launch_bounds__(NTHREADS, 1)
void rnn_rec_kernel(const float* __restrict__ x,      // [B, T, 1]
                    const float* __restrict__ W_ih,   // [H, 1]
                    const float* __restrict__ W_hh,   // [H, H]
                    const float* __restrict__ b_ih,   // [H]
                    const float* __restrict__ b_hh)   // [H]
{
    __shared__ __align__(16) float xs[BPC][TT];        // 8 KB input preload
    __shared__ __align__(16) float hs[2][BPC][HH];     // double-buffered h

    const int tid = threadIdx.x;
    const int bl  = tid >> 7;         // batch-local 0/1
    const int h   = tid & (HH - 1);
    const int b   = blockIdx.x * BPC + bl;
    const int bar = bl + 1;           // named barrier id: this row's 4 warps

    // ---- W_hh row h -> 64 packed f32x2 registers ----
    unsigned long long w[HH / 2];
    {
        const ulonglong2* wrow = (const ulonglong2*)(W_hh + h * HH);
        #pragma unroll
        for (int j = 0; j < HH / 4; j++) {
            ulonglong2 v = wrow[j];
            w[2 * j]     = v.x;
            w[2 * j + 1] = v.y;
        }
    }
    const float wih  = W_ih[h];
    const float bias = b_ih[h] + b_hh[h];

    // ---- preload x for this row (group-local; covered by named barrier) ----
    for (int i = h; i < TT; i += HH)
        xs[bl][i] = x[b * TT + i];

    hs[0][bl][h] = 0.0f;

    // ---- anti-phase skew: row 1 burns ~320 cycles (80 dependent FMAs)
    // before its first barrier. Deterministic; guard is never true at
    // runtime (|bias| < 0.2 stays ~bias under near-identity iterations)
    // but defeats dead-code elimination.
    if (bl) {
        float z = bias;
        #pragma unroll
        for (int i = 0; i < 80; i++)
            z = fmaf(z, 1.0000001f, 1e-30f);
        if (z == 1234567.0f) xs[1][0] = z;
    }

    asm volatile("bar.sync %0, 128;" :: "r"(bar) : "memory");

    __half* hout = g_hseq_h + (size_t)b * TT * HH + h;

    for (int t = 0; t < TT; t++) {
        const int cur = t & 1;
        const int nxt = cur ^ 1;

        // x-projection + bias folded into accumulator init (off critical tail)
        const float xb = fmaf(xs[bl][t], wih, bias);

        // 128-wide dot via packed f32x2 FMA, 4 independent chains
        unsigned long long a0 = pack2(xb, 0.0f);
        unsigned long long a1 = 0ull, a2 = 0ull, a3 = 0ull;
        const ulonglong2* hv = (const ulonglong2*)&hs[cur][bl][0];
        #pragma unroll
        for (int j = 0; j < HH / 4; j += 2) {
            ulonglong2 p = hv[j];
            a0 = ffma2(p.x, w[2 * j],     a0);
            a1 = ffma2(p.y, w[2 * j + 1], a1);
            ulonglong2 q = hv[j + 1];
            a2 = ffma2(q.x, w[2 * j + 2], a2);
            a3 = ffma2(q.y, w[2 * j + 3], a3);
        }
        unsigned long long s = addf2(addf2(a0, a1), addf2(a2, a3));
        float2 f  = unpack_f32x2(s);
        float pre = f.x + f.y;

        // tanh(x) = 1 - 2/(exp(2x)+1)   (EX2 + RCP, ~1e-6 rel err; safe vs
        // MUFU.TANH whose ~5e-4 abs err compounds over 1024 steps)
        float e  = __expf(pre + pre);
        float hn = 1.0f - __fdividef(2.0f, e + 1.0f);

        hs[nxt][bl][h] = hn;
        hout[(size_t)t * HH] = __float2half(hn);   // fp16 export for fc

        asm volatile("bar.sync %0, 128;" :: "r"(bar) : "memory");
    }
}

// ---------------------------------------------------------------------------
// Kernel 2: streaming logits from fp16 hidden states (64 MB total).
// out[b,t,c] = sum_h h[b,t,h]*W_fc[c,h] + b_fc[c];  fp32 accumulation.
// ---------------------------------------------------------------------------
__global__ __launch_bounds__(K2_THREADS)
void rnn_fc_kernel(const float* __restrict__ W_fc,   // [2, H]
                   const float* __restrict__ b_fc,   // [2]
                   float* __restrict__ out)          // [B, T, 2]
{
    __shared__ __align__(16) float wf[2][HH];
    __shared__ float bf[2];

    const int tid = threadIdx.x;
    if (tid < HH) {
        wf[0][tid] = W_fc[tid];
        wf[1][tid] = W_fc[HH + tid];
    }
    if (tid < 2) bf[tid] = b_fc[tid];
    __syncthreads();

    const size_t r = (size_t)blockIdx.x * K2_THREADS + tid;   // row in [0, B*T)
    const uint4* hv = (const uint4*)(g_hseq_h + r * HH);      // 16 x 16B = 128 halves

    float acc0 = 0.0f, acc1 = 0.0f;
    #pragma unroll
    for (int j = 0; j < HH / 8; j++) {          // 16 LDG.128
        uint4 v = __ldcs(&hv[j]);
        const __half2* hp = (const __half2*)&v;
        #pragma unroll
        for (int k = 0; k < 4; k++) {
            float2 hf = __half22float2(hp[k]);
            int idx = j * 8 + k * 2;
            acc0 = fmaf(hf.x, wf[0][idx],     acc0);
            acc0 = fmaf(hf.y, wf[0][idx + 1], acc0);
            acc1 = fmaf(hf.x, wf[1][idx],     acc1);
            acc1 = fmaf(hf.y, wf[1][idx + 1], acc1);
        }
    }
    float2 res = make_float2(acc0 + bf[0], acc1 + bf[1]);
    ((float2*)out)[r] = res;           // coalesced 8B/thread
}

extern "C" void kernel_launch(void* const* d_in, const int* in_sizes, int n_in,
                              void* d_out, int out_size) {
    const float* x    = (const float*)d_in[0];
    const float* W_ih = (const float*)d_in[1];
    const float* W_hh = (const float*)d_in[2];
    const float* b_ih = (const float*)d_in[3];
    const float* b_hh = (const float*)d_in[4];
    const float* W_fc = (const float*)d_in[5];
    const float* b_fc = (const float*)d_in[6];
    float* out = (float*)d_out;

    rnn_rec_kernel<<<BB / BPC, NTHREADS>>>(x, W_ih, W_hh, b_ih, b_hh);
    rnn_fc_kernel<<<(BB * TT) / K2_THREADS, K2_THREADS>>>(W_fc, b_fc, out);
}

// round 15
// speedup vs baseline: 2.2102x; 1.3268x over previous
#include <cuda_runtime.h>
#include <cuda_fp16.h>

#define TT 1024
#define HH 128
#define BB 256
#define BPC 2            // batch rows per CTA
#define NTHREADS 256
#define K2_THREADS 256
#define CHUNK_F 36       // 32 floats + 4 pad -> 144B stride, bank-disjoint kq streams

// 256*1024*128 halves = 64 MB scratch for hidden-state sequence [B,T,H]
__device__ __half g_hseq_h[(size_t)BB * TT * HH];

__device__ __forceinline__ unsigned long long ffma2(unsigned long long a,
                                                    unsigned long long b,
                                                    unsigned long long c) {
    unsigned long long d;
    asm("fma.rn.f32x2 %0, %1, %2, %3;" : "=l"(d) : "l"(a), "l"(b), "l"(c));
    return d;
}

__device__ __forceinline__ float2 unpack_f32x2(unsigned long long v) {
    float2 f;
    asm("mov.b64 {%0, %1}, %2;" : "=f"(f.x), "=f"(f.y) : "l"(v));
    return f;
}

// ---------------------------------------------------------------------------
// Kernel 1: serial recurrence. One CTA = 2 batch rows, 128 threads/row.
// k-split decomposition: lane (quad,kq) computes partials for units
// 32*warp+4*quad+{0..3} over k-chunk [32*kq, 32*kq+32). Each loaded h-pair
// is reused across 4 register-resident FFMA chains -> 4x less LDS traffic.
// 2-round shfl butterfly combines the 4 kq partials; lane l finalizes unit l.
// ---------------------------------------------------------------------------
__global__ __launch_bounds__(NTHREADS, 1)
void rnn_rec_kernel(const float* __restrict__ x,      // [B, T, 1]
                    const float* __restrict__ W_ih,   // [H, 1]
                    const float* __restrict__ W_hh,   // [H, H]
                    const float* __restrict__ b_ih,   // [H]
                    const float* __restrict__ b_hh)   // [H]
{
    __shared__ __align__(16) float xs[BPC][TT];                 // 8 KB input preload
    __shared__ __align__(16) float hs[2][BPC][4 * CHUNK_F];     // padded h chunks

    const int tid  = threadIdx.x;
    const int bl   = tid >> 7;          // batch-local row 0/1
    const int r    = tid & 127;         // thread id within row
    const int wid  = r >> 5;            // warp within row (0..3)
    const int lane = r & 31;
    const int quad = lane >> 2;         // unit-quad (0..7)
    const int kq   = lane & 3;          // k-chunk (0..3)
    const int b    = blockIdx.x * BPC + bl;
    const int bar  = bl + 1;            // named barrier: this row's 4 warps

    const int u      = wid * 32 + lane;        // finalize unit (== chunk wid, pos lane)
    const int ubase  = wid * 32 + quad * 4;    // first FFMA unit
    const int k0     = kq * 32;                // my k-chunk start

    // ---- weights: 4 units x 32 k -> 4 x 16 packed f32x2 registers ----
    unsigned long long w0[16], w1[16], w2[16], w3[16];
    {
        #pragma unroll
        for (int c = 0; c < 4; c++) {
            const ulonglong2* p =
                (const ulonglong2*)(W_hh + (ubase + c) * HH + k0);
            unsigned long long* wc = (c == 0) ? w0 : (c == 1) ? w1 : (c == 2) ? w2 : w3;
            #pragma unroll
            for (int j = 0; j < 8; j++) {
                ulonglong2 v = p[j];
                wc[2 * j]     = v.x;
                wc[2 * j + 1] = v.y;
            }
        }
    }
    const float wih  = W_ih[u];
    const float bias = b_ih[u] + b_hh[u];

    // ---- preload x for this row ----
    for (int i = r; i < TT; i += 128)
        xs[bl][i] = x[b * TT + i];

    // ---- zero h (incl. pads) ----
    for (int i = r; i < 4 * CHUNK_F; i += 128)
        hs[0][bl][i] = 0.0f;

    asm volatile("bar.sync %0, 128;" :: "r"(bar) : "memory");

    __half* hout = g_hseq_h + (size_t)b * TT * HH + u;

    for (int t = 0; t < TT; t++) {
        const int cur = t & 1;
        const int nxt = cur ^ 1;

        const float xb = fmaf(xs[bl][t], wih, bias);   // off critical tail

        // ---- load my 32-float k-chunk (8 LDS.128, bank-disjoint across kq) ----
        unsigned long long hreg[16];
        {
            const ulonglong2* hv =
                (const ulonglong2*)&hs[cur][bl][kq * CHUNK_F];
            #pragma unroll
            for (int j = 0; j < 8; j++) {
                ulonglong2 v = hv[j];
                hreg[2 * j]     = v.x;
                hreg[2 * j + 1] = v.y;
            }
        }

        // ---- 4 independent 16-deep packed FMA chains (h reused x4) ----
        unsigned long long a0 = 0ull, a1 = 0ull, a2 = 0ull, a3 = 0ull;
        #pragma unroll
        for (int j = 0; j < 16; j++) {
            a0 = ffma2(hreg[j], w0[j], a0);
            a1 = ffma2(hreg[j], w1[j], a1);
            a2 = ffma2(hreg[j], w2[j], a2);
            a3 = ffma2(hreg[j], w3[j], a3);
        }
        float2 f0 = unpack_f32x2(a0);
        float2 f1 = unpack_f32x2(a1);
        float2 f2 = unpack_f32x2(a2);
        float2 f3 = unpack_f32x2(a3);
        float s0 = f0.x + f0.y;
        float s1 = f1.x + f1.y;
        float s2 = f2.x + f2.y;
        float s3 = f3.x + f3.y;

        // ---- combine the 4 kq partials (butterfly within quad lanes) ----
        s0 += __shfl_xor_sync(0xffffffffu, s0, 1);
        s1 += __shfl_xor_sync(0xffffffffu, s1, 1);
        s2 += __shfl_xor_sync(0xffffffffu, s2, 1);
        s3 += __shfl_xor_sync(0xffffffffu, s3, 1);
        s0 += __shfl_xor_sync(0xffffffffu, s0, 2);
        s1 += __shfl_xor_sync(0xffffffffu, s1, 2);
        s2 += __shfl_xor_sync(0xffffffffu, s2, 2);
        s3 += __shfl_xor_sync(0xffffffffu, s3, 2);

        // lane kq finalizes unit ubase+kq == unit u
        float sA  = (kq & 1) ? s1 : s0;
        float sB  = (kq & 1) ? s3 : s2;
        float s   = (kq & 2) ? sB : sA;
        float pre = s + xb;

        // tanh(x) = 1 - 2/(exp(2x)+1)   (EX2 + RCP, ~1e-6 rel err)
        float e  = __expf(pre + pre);
        float hn = 1.0f - __fdividef(2.0f, e + 1.0f);

        // store: chunk wid, pos lane (conflict-free 128B per warp)
        hs[nxt][bl][wid * CHUNK_F + lane] = hn;
        hout[(size_t)t * HH] = __float2half(hn);    // coalesced 64B/warp

        asm volatile("bar.sync %0, 128;" :: "r"(bar) : "memory");
    }
}

// ---------------------------------------------------------------------------
// Kernel 2: streaming logits from fp16 hidden states (64 MB total).
// out[b,t,c] = sum_h h[b,t,h]*W_fc[c,h] + b_fc[c];  fp32 accumulation.
// ---------------------------------------------------------------------------
__global__ __launch_bounds__(K2_THREADS)
void rnn_fc_kernel(const float* __restrict__ W_fc,   // [2, H]
                   const float* __restrict__ b_fc,   // [2]
                   float* __restrict__ out)          // [B, T, 2]
{
    __shared__ __align__(16) float wf[2][HH];
    __shared__ float bf[2];

    const int tid = threadIdx.x;
    if (tid < HH) {
        wf[0][tid] = W_fc[tid];
        wf[1][tid] = W_fc[HH + tid];
    }
    if (tid < 2) bf[tid] = b_fc[tid];
    __syncthreads();

    const size_t r = (size_t)blockIdx.x * K2_THREADS + tid;   // row in [0, B*T)
    const uint4* hv = (const uint4*)(g_hseq_h + r * HH);      // 16 x 16B

    float acc0 = 0.0f, acc1 = 0.0f;
    #pragma unroll
    for (int j = 0; j < HH / 8; j++) {          // 16 LDG.128
        uint4 v = __ldcs(&hv[j]);
        const __half2* hp = (const __half2*)&v;
        #pragma unroll
        for (int k = 0; k < 4; k++) {
            float2 hf = __half22float2(hp[k]);
            int idx = j * 8 + k * 2;
            acc0 = fmaf(hf.x, wf[0][idx],     acc0);
            acc0 = fmaf(hf.y, wf[0][idx + 1], acc0);
            acc1 = fmaf(hf.x, wf[1][idx],     acc1);
            acc1 = fmaf(hf.y, wf[1][idx + 1], acc1);
        }
    }
    float2 res = make_float2(acc0 + bf[0], acc1 + bf[1]);
    ((float2*)out)[r] = res;           // coalesced 8B/thread
}

extern "C" void kernel_launch(void* const* d_in, const int* in_sizes, int n_in,
                              void* d_out, int out_size) {
    const float* x    = (const float*)d_in[0];
    const float* W_ih = (const float*)d_in[1];
    const float* W_hh = (const float*)d_in[2];
    const float* b_ih = (const float*)d_in[3];
    const float* b_hh = (const float*)d_in[4];
    const float* W_fc = (const float*)d_in[5];
    const float* b_fc = (const float*)d_in[6];
    float* out = (float*)d_out;

    rnn_rec_kernel<<<BB / BPC, NTHREADS>>>(x, W_ih, W_hh, b_ih, b_hh);
    rnn_fc_kernel<<<(BB * TT) / K2_THREADS, K2_THREADS>>>(W_fc, b_fc, out);
}

// round 16
// speedup vs baseline: 2.2204x; 1.0046x over previous
#include <cuda_runtime.h>
#include <cuda_fp16.h>

#define TT 1024
#define HH 128
#define BB 256
#define BPC 2            // batch rows per CTA
#define NTHREADS 256
#define K2_THREADS 256
#define CHUNK_F 36       // 32 floats + 4 pad -> 144B stride, bank-disjoint kq streams

// 256*1024*128 halves = 64 MB scratch for hidden-state sequence [B,T,H]
__device__ __half g_hseq_h[(size_t)BB * TT * HH];

__device__ __forceinline__ unsigned long long ffma2(unsigned long long a,
                                                    unsigned long long b,
                                                    unsigned long long c) {
    unsigned long long d;
    asm("fma.rn.f32x2 %0, %1, %2, %3;" : "=l"(d) : "l"(a), "l"(b), "l"(c));
    return d;
}

__device__ __forceinline__ float2 unpack_f32x2(unsigned long long v) {
    float2 f;
    asm("mov.b64 {%0, %1}, %2;" : "=f"(f.x), "=f"(f.y) : "l"(v));
    return f;
}

// ---------------------------------------------------------------------------
// Kernel 1: serial recurrence. One CTA = 2 batch rows, 128 threads/row,
// rows decoupled via private named barriers. k-split decomposition (R15):
// lane (quad,kq) computes partials for units 32*warp+4*quad+{0..3} over
// k-chunk [32*kq, +32); 2-round shfl butterfly combines; lane kq finalizes.
// NEW: row 1 runs ~250 cycles of deterministic delay before its first
// barrier -> persistent anti-phase, so each SMSP overlaps one row's FMA
// burst with the other row's serial tail (valid now that the SM-wide LDS
// crossbar floor from pre-R15 kernels is gone).
// ---------------------------------------------------------------------------
__global__ __launch_bounds__(NTHREADS, 1)
void rnn_rec_kernel(const float* __restrict__ x,      // [B, T, 1]
                    const float* __restrict__ W_ih,   // [H, 1]
                    const float* __restrict__ W_hh,   // [H, H]
                    const float* __restrict__ b_ih,   // [H]
                    const float* __restrict__ b_hh)   // [H]
{
    __shared__ __align__(16) float xs[BPC][TT];                 // 8 KB input preload
    __shared__ __align__(16) float hs[2][BPC][4 * CHUNK_F];     // padded h chunks

    const int tid  = threadIdx.x;
    const int bl   = tid >> 7;          // batch-local row 0/1
    const int r    = tid & 127;         // thread id within row
    const int wid  = r >> 5;            // warp within row (0..3)
    const int lane = r & 31;
    const int quad = lane >> 2;         // unit-quad (0..7)
    const int kq   = lane & 3;          // k-chunk (0..3)
    const int b    = blockIdx.x * BPC + bl;
    const int bar  = bl + 1;            // named barrier: this row's 4 warps

    const int u      = wid * 32 + lane;        // finalize unit
    const int ubase  = wid * 32 + quad * 4;    // first FFMA unit
    const int k0     = kq * 32;                // my k-chunk start

    // ---- weights: 4 units x 32 k -> 4 x 16 packed f32x2 registers ----
    unsigned long long w0[16], w1[16], w2[16], w3[16];
    {
        #pragma unroll
        for (int c = 0; c < 4; c++) {
            const ulonglong2* p =
                (const ulonglong2*)(W_hh + (ubase + c) * HH + k0);
            unsigned long long* wc = (c == 0) ? w0 : (c == 1) ? w1 : (c == 2) ? w2 : w3;
            #pragma unroll
            for (int j = 0; j < 8; j++) {
                ulonglong2 v = p[j];
                wc[2 * j]     = v.x;
                wc[2 * j + 1] = v.y;
            }
        }
    }
    const float wih  = W_ih[u];
    const float bias = b_ih[u] + b_hh[u];

    // ---- preload x for this row ----
    for (int i = r; i < TT; i += 128)
        xs[bl][i] = x[b * TT + i];

    // ---- zero h (incl. pads) ----
    for (int i = r; i < 4 * CHUNK_F; i += 128)
        hs[0][bl][i] = 0.0f;

    // ---- anti-phase skew: row 1 burns ~250 cycles (64 dependent FMAs)
    // before its first barrier. Deterministic; the guard is never true at
    // runtime but defeats dead-code elimination.
    if (bl) {
        float z = bias;
        #pragma unroll
        for (int i = 0; i < 64; i++)
            z = fmaf(z, 1.0000001f, 1e-30f);
        if (z == 1234567.0f) xs[1][0] = z;
    }

    asm volatile("bar.sync %0, 128;" :: "r"(bar) : "memory");

    __half* hout = g_hseq_h + (size_t)b * TT * HH + u;

    for (int t = 0; t < TT; t++) {
        const int cur = t & 1;
        const int nxt = cur ^ 1;

        const float xb = fmaf(xs[bl][t], wih, bias);   // off critical tail

        // ---- load my 32-float k-chunk (8 LDS.128, bank-disjoint across kq) ----
        unsigned long long hreg[16];
        {
            const ulonglong2* hv =
                (const ulonglong2*)&hs[cur][bl][kq * CHUNK_F];
            #pragma unroll
            for (int j = 0; j < 8; j++) {
                ulonglong2 v = hv[j];
                hreg[2 * j]     = v.x;
                hreg[2 * j + 1] = v.y;
            }
        }

        // ---- 4 independent 16-deep packed FMA chains (h reused x4) ----
        unsigned long long a0 = 0ull, a1 = 0ull, a2 = 0ull, a3 = 0ull;
        #pragma unroll
        for (int j = 0; j < 16; j++) {
            a0 = ffma2(hreg[j], w0[j], a0);
            a1 = ffma2(hreg[j], w1[j], a1);
            a2 = ffma2(hreg[j], w2[j], a2);
            a3 = ffma2(hreg[j], w3[j], a3);
        }
        float2 f0 = unpack_f32x2(a0);
        float2 f1 = unpack_f32x2(a1);
        float2 f2 = unpack_f32x2(a2);
        float2 f3 = unpack_f32x2(a3);
        float s0 = f0.x + f0.y;
        float s1 = f1.x + f1.y;
        float s2 = f2.x + f2.y;
        float s3 = f3.x + f3.y;

        // ---- combine the 4 kq partials (butterfly within quad lanes) ----
        s0 += __shfl_xor_sync(0xffffffffu, s0, 1);
        s1 += __shfl_xor_sync(0xffffffffu, s1, 1);
        s2 += __shfl_xor_sync(0xffffffffu, s2, 1);
        s3 += __shfl_xor_sync(0xffffffffu, s3, 1);
        s0 += __shfl_xor_sync(0xffffffffu, s0, 2);
        s1 += __shfl_xor_sync(0xffffffffu, s1, 2);
        s2 += __shfl_xor_sync(0xffffffffu, s2, 2);
        s3 += __shfl_xor_sync(0xffffffffu, s3, 2);

        // lane kq finalizes unit ubase+kq == unit u
        float sA  = (kq & 1) ? s1 : s0;
        float sB  = (kq & 1) ? s3 : s2;
        float s   = (kq & 2) ? sB : sA;
        float pre = s + xb;

        // tanh(x) = 1 - 2/(exp(2x)+1)   (EX2 + RCP, ~1e-6 rel err)
        float e  = __expf(pre + pre);
        float hn = 1.0f - __fdividef(2.0f, e + 1.0f);

        // store: chunk wid, pos lane (conflict-free 128B per warp)
        hs[nxt][bl][wid * CHUNK_F + lane] = hn;
        hout[(size_t)t * HH] = __float2half(hn);    // coalesced 64B/warp

        asm volatile("bar.sync %0, 128;" :: "r"(bar) : "memory");
    }
}

// ---------------------------------------------------------------------------
// Kernel 2: streaming logits from fp16 hidden states (64 MB total).
// out[b,t,c] = sum_h h[b,t,h]*W_fc[c,h] + b_fc[c];  fp32 accumulation.
// ---------------------------------------------------------------------------
__global__ __launch_bounds__(K2_THREADS)
void rnn_fc_kernel(const float* __restrict__ W_fc,   // [2, H]
                   const float* __restrict__ b_fc,   // [2]
                   float* __restrict__ out)          // [B, T, 2]
{
    __shared__ __align__(16) float wf[2][HH];
    __shared__ float bf[2];

    const int tid = threadIdx.x;
    if (tid < HH) {
        wf[0][tid] = W_fc[tid];
        wf[1][tid] = W_fc[HH + tid];
    }
    if (tid < 2) bf[tid] = b_fc[tid];
    __syncthreads();

    const size_t r = (size_t)blockIdx.x * K2_THREADS + tid;   // row in [0, B*T)
    const uint4* hv = (const uint4*)(g_hseq_h + r * HH);      // 16 x 16B

    float acc0 = 0.0f, acc1 = 0.0f;
    #pragma unroll
    for (int j = 0; j < HH / 8; j++) {          // 16 LDG.128
        uint4 v = __ldcs(&hv[j]);
        const __half2* hp = (const __half2*)&v;
        #pragma unroll
        for (int k = 0; k < 4; k++) {
            float2 hf = __half22float2(hp[k]);
            int idx = j * 8 + k * 2;
            acc0 = fmaf(hf.x, wf[0][idx],     acc0);
            acc0 = fmaf(hf.y, wf[0][idx + 1], acc0);
            acc1 = fmaf(hf.x, wf[1][idx],     acc1);
            acc1 = fmaf(hf.y, wf[1][idx + 1], acc1);
        }
    }
    float2 res = make_float2(acc0 + bf[0], acc1 + bf[1]);
    ((float2*)out)[r] = res;           // coalesced 8B/thread
}

extern "C" void kernel_launch(void* const* d_in, const int* in_sizes, int n_in,
                              void* d_out, int out_size) {
    const float* x    = (const float*)d_in[0];
    const float* W_ih = (const float*)d_in[1];
    const float* W_hh = (const float*)d_in[2];
    const float* b_ih = (const float*)d_in[3];
    const float* b_hh = (const float*)d_in[4];
    const float* W_fc = (const float*)d_in[5];
    const float* b_fc = (const float*)d_in[6];
    float* out = (float*)d_out;

    rnn_rec_kernel<<<BB / BPC, NTHREADS>>>(x, W_ih, W_hh, b_ih, b_hh);
    rnn_fc_kernel<<<(BB * TT) / K2_THREADS, K2_THREADS>>>(W_fc, b_fc, out);
}